// round 2
// baseline (speedup 1.0000x reference)
#include <cuda_runtime.h>
#include <math.h>
#include <limits.h>

#define BB 32
#define HH 512
#define EE 512
#define VV 10000
#define FF 1280
#define PP 196
#define TT 80
#define G4 2048                  // 4*H
#define XD 1792                  // E+F
#define NBLK_LOG ((VV + 63) / 64)  // 157

// ---------------- scratch (static device globals; no runtime allocation) ---
__device__ float g_mean[BB * FF];
__device__ float g_h[BB * HH];
__device__ float g_c[BB * HH];
__device__ float g_inp[BB * EE];
__device__ float g_hid[BB * HH];
__device__ float g_glin[BB * FF];
__device__ float g_g0[BB * G4];
__device__ float g_gates[BB * G4];
__device__ float g_w[BB * PP];
__device__ float g_ctx[BB * FF];
__device__ float g_encproj[BB * PP * HH];     // 12.85 MB
__device__ float g_bmv[BB * NBLK_LOG];
__device__ int   g_bmi[BB * NBLK_LOG];

__device__ __forceinline__ float sigmoidf(float x) { return 1.0f / (1.0f + expf(-x)); }

// ---------------------------------------------------------------------------
// gemm32 core: C_tile[32 x 64] += A[32,K] * W[col,:]^T  (both K-contiguous)
// blockDim must be 128.  K % 32 == 0.  nvalid <= 64 clamps columns (for V tail).
// smem layout: As[k][row] (32x33), Ws[k][col] (32x66)
// ---------------------------------------------------------------------------
#define SM_FLOATS (32 * 33 + 32 * 66)

__device__ __forceinline__ void gemm32_core(
    const float* __restrict__ A, int lda,
    const float* __restrict__ W, int ldw,
    int K, int col0, int nvalid,
    float acc[8][2], float* As, float* Ws)
{
    const int tid = threadIdx.x;   // 0..127
    const int tx  = tid & 31;
    const int rq  = tid >> 5;

    for (int k0 = 0; k0 < K; k0 += 32) {
        __syncthreads();
        // A chunk: 32 rows x 32 k = 1024 floats = 256 float4, 2 per thread
        #pragma unroll
        for (int v = 0; v < 2; ++v) {
            int idx = tid + v * 128;          // 0..255
            int row = idx >> 3;
            int kq  = idx & 7;
            const float4 a = *(const float4*)(A + (size_t)row * lda + k0 + kq * 4);
            As[(kq * 4 + 0) * 33 + row] = a.x;
            As[(kq * 4 + 1) * 33 + row] = a.y;
            As[(kq * 4 + 2) * 33 + row] = a.z;
            As[(kq * 4 + 3) * 33 + row] = a.w;
        }
        // W chunk: 64 cols x 32 k = 2048 floats = 512 float4, 4 per thread
        #pragma unroll
        for (int v = 0; v < 4; ++v) {
            int idx = tid + v * 128;          // 0..511
            int col = idx >> 3;
            int kq  = idx & 7;
            float4 w = make_float4(0.f, 0.f, 0.f, 0.f);
            if (col < nvalid)
                w = *(const float4*)(W + (size_t)(col0 + col) * ldw + k0 + kq * 4);
            Ws[(kq * 4 + 0) * 66 + col] = w.x;
            Ws[(kq * 4 + 1) * 66 + col] = w.y;
            Ws[(kq * 4 + 2) * 66 + col] = w.z;
            Ws[(kq * 4 + 3) * 66 + col] = w.w;
        }
        __syncthreads();
        #pragma unroll
        for (int k = 0; k < 32; ++k) {
            const float2 w2 = *(const float2*)(&Ws[k * 66 + tx * 2]);
            #pragma unroll
            for (int i = 0; i < 8; ++i) {
                float a = As[k * 33 + rq * 8 + i];
                acc[i][0] += a * w2.x;
                acc[i][1] += a * w2.y;
            }
        }
    }
}

__device__ __forceinline__ void acc_zero(float acc[8][2]) {
    #pragma unroll
    for (int i = 0; i < 8; ++i) { acc[i][0] = 0.f; acc[i][1] = 0.f; }
}

// ---------------------------------------------------------------------------
// setup kernels
// ---------------------------------------------------------------------------
__global__ void k_mean(const float* __restrict__ feat) {
    int idx = blockIdx.x * 256 + threadIdx.x;       // BB*FF = 40960
    if (idx >= BB * FF) return;
    int b = idx / FF, f = idx % FF;
    const float* p0 = feat + (size_t)b * PP * FF + f;
    float s = 0.f;
    for (int p = 0; p < PP; ++p) s += p0[(size_t)p * FF];
    g_mean[idx] = s * (1.0f / PP);
}

__global__ void k_inithc(const float* __restrict__ ihw, const float* __restrict__ ihb,
                         const float* __restrict__ icw, const float* __restrict__ icb) {
    __shared__ float sm[SM_FLOATS];
    float acc[8][2]; acc_zero(acc);
    int bx = blockIdx.x;
    bool ish = bx < 8;
    int col0 = (ish ? bx : bx - 8) * 64;
    const float* W = ish ? ihw : icw;
    const float* bias = ish ? ihb : icb;
    float* C = ish ? g_h : g_c;
    gemm32_core(g_mean, FF, W, FF, FF, col0, 64, acc, sm, sm + 32 * 33);
    const int tx = threadIdx.x & 31, rq = threadIdx.x >> 5;
    #pragma unroll
    for (int i = 0; i < 8; ++i)
        #pragma unroll
        for (int j = 0; j < 2; ++j) {
            int c = col0 + tx * 2 + j;
            C[(rq * 8 + i) * HH + c] = acc[i][j] + bias[c];
        }
}

__global__ void k_inp0(const float* __restrict__ emb) {
    int idx = blockIdx.x * 256 + threadIdx.x;      // BB*EE = 16384
    if (idx >= BB * EE) return;
    int e = idx & (EE - 1);
    g_inp[idx] = emb[(size_t)1 * EE + e];          // SOS = 1
}

__global__ void k_encproj(const float* __restrict__ feat,
                          const float* __restrict__ W2_w, const float* __restrict__ W2_b) {
    __shared__ float sm[SM_FLOATS];
    float acc[8][2]; acc_zero(acc);
    int col0 = blockIdx.x * 64;
    int m0 = blockIdx.y * 32;
    gemm32_core(feat + (size_t)m0 * FF, FF, W2_w, FF, FF, col0, 64, acc, sm, sm + 32 * 33);
    const int tx = threadIdx.x & 31, rq = threadIdx.x >> 5;
    #pragma unroll
    for (int i = 0; i < 8; ++i)
        #pragma unroll
        for (int j = 0; j < 2; ++j) {
            int c = col0 + tx * 2 + j;
            g_encproj[(size_t)(m0 + rq * 8 + i) * HH + c] = acc[i][j] + W2_b[c];
        }
}

// ---------------------------------------------------------------------------
// per-step kernels
// ---------------------------------------------------------------------------
// S1: hid = h@W1^T+b1 ; glin = h@gate_w^T+gate_b ; g0 = h@Whh^T + inp@WihE^T + bih + bhh
__global__ void k_hproj(const float* __restrict__ W1_w, const float* __restrict__ W1_b,
                        const float* __restrict__ gate_w, const float* __restrict__ gate_b,
                        const float* __restrict__ Whh, const float* __restrict__ Wih,
                        const float* __restrict__ bih, const float* __restrict__ bhh) {
    __shared__ float sm[SM_FLOATS];
    float acc[8][2]; acc_zero(acc);
    const int bx = blockIdx.x;
    const int tx = threadIdx.x & 31, rq = threadIdx.x >> 5;
    if (bx < 8) {
        int col0 = bx * 64;
        gemm32_core(g_h, HH, W1_w, HH, HH, col0, 64, acc, sm, sm + 32 * 33);
        #pragma unroll
        for (int i = 0; i < 8; ++i)
            #pragma unroll
            for (int j = 0; j < 2; ++j) {
                int c = col0 + tx * 2 + j;
                g_hid[(rq * 8 + i) * HH + c] = acc[i][j] + W1_b[c];
            }
    } else if (bx < 28) {
        int col0 = (bx - 8) * 64;
        gemm32_core(g_h, HH, gate_w, HH, HH, col0, 64, acc, sm, sm + 32 * 33);
        #pragma unroll
        for (int i = 0; i < 8; ++i)
            #pragma unroll
            for (int j = 0; j < 2; ++j) {
                int c = col0 + tx * 2 + j;
                g_glin[(rq * 8 + i) * FF + c] = acc[i][j] + gate_b[c];
            }
    } else {
        int col0 = (bx - 28) * 64;
        gemm32_core(g_h, HH, Whh, HH, HH, col0, 64, acc, sm, sm + 32 * 33);
        gemm32_core(g_inp, EE, Wih, XD, EE, col0, 64, acc, sm, sm + 32 * 33);
        #pragma unroll
        for (int i = 0; i < 8; ++i)
            #pragma unroll
            for (int j = 0; j < 2; ++j) {
                int c = col0 + tx * 2 + j;
                g_g0[(rq * 8 + i) * G4 + c] = acc[i][j] + bih[c] + bhh[c];
            }
    }
}

// S2a: scores + softmax -> weights (g_w and attentions output)
__global__ void k_attn(const float* __restrict__ Va_w, const float* __restrict__ Va_b,
                       float* __restrict__ attn_t /* attn + t*PP */) {
    const int b = blockIdx.x;
    const int tid = threadIdx.x;                   // 256
    __shared__ float hid_s[HH], va_s[HH], sc[PP], red[256];
    for (int i = tid; i < HH; i += 256) { hid_s[i] = g_hid[b * HH + i]; va_s[i] = Va_w[i]; }
    __syncthreads();
    const int wid = tid >> 5, ln = tid & 31;
    for (int p = wid; p < PP; p += 8) {
        const float* ep = g_encproj + ((size_t)b * PP + p) * HH;
        float s = 0.f;
        for (int h = ln; h < HH; h += 32) {
            float t0 = hid_s[h] + ep[h];
            if (t0 > 0.f) s += t0 * va_s[h];
        }
        #pragma unroll
        for (int off = 16; off; off >>= 1) s += __shfl_xor_sync(0xffffffffu, s, off);
        if (ln == 0) sc[p] = s + Va_b[0];
    }
    __syncthreads();
    // softmax over PP=196
    float v = (tid < PP) ? sc[tid] : -INFINITY;
    red[tid] = v; __syncthreads();
    for (int st = 128; st > 0; st >>= 1) { if (tid < st) red[tid] = fmaxf(red[tid], red[tid + st]); __syncthreads(); }
    float mx = red[0];
    __syncthreads();
    float e = (tid < PP) ? expf(v - mx) : 0.f;
    red[tid] = e; __syncthreads();
    for (int st = 128; st > 0; st >>= 1) { if (tid < st) red[tid] += red[tid + st]; __syncthreads(); }
    float inv = 1.0f / red[0];
    if (tid < PP) {
        float w = e * inv;
        g_w[b * PP + tid] = w;
        attn_t[(size_t)b * TT * PP + tid] = w;
    }
}

// S2b: context = weights^T @ features ; apply sigmoid gate
__global__ void k_context(const float* __restrict__ feat) {
    const int bx = blockIdx.x;                     // 32*10
    const int b = bx / 10, f0 = (bx % 10) * 128;
    const int tid = threadIdx.x;                   // 128
    __shared__ float ws[PP];
    for (int i = tid; i < PP; i += 128) ws[i] = g_w[b * PP + i];
    __syncthreads();
    const int f = f0 + tid;
    const float* fb = feat + (size_t)b * PP * FF + f;
    float acc = 0.f;
    for (int p = 0; p < PP; ++p) acc += ws[p] * fb[(size_t)p * FF];
    float gl = g_glin[b * FF + f];
    g_ctx[b * FF + f] = acc * sigmoidf(gl);
}

// S3: gates = g0 + ctx @ WihF^T
__global__ void k_gates(const float* __restrict__ Wih) {
    __shared__ float sm[SM_FLOATS];
    float acc[8][2]; acc_zero(acc);
    int col0 = blockIdx.x * 64;                    // 32 blocks
    gemm32_core(g_ctx, FF, Wih + EE, XD, FF, col0, 64, acc, sm, sm + 32 * 33);
    const int tx = threadIdx.x & 31, rq = threadIdx.x >> 5;
    #pragma unroll
    for (int i = 0; i < 8; ++i)
        #pragma unroll
        for (int j = 0; j < 2; ++j) {
            int c = col0 + tx * 2 + j;
            int r = rq * 8 + i;
            g_gates[r * G4 + c] = acc[i][j] + g_g0[r * G4 + c];
        }
}

// S4: LSTM elementwise
__global__ void k_lstm() {
    int idx = blockIdx.x * 256 + threadIdx.x;      // BB*HH = 16384
    if (idx >= BB * HH) return;
    int b = idx >> 9, j = idx & 511;
    const float* g = g_gates + b * G4;
    float ig = sigmoidf(g[j]);
    float fg = sigmoidf(g[j + 512]);
    float gg = tanhf(g[j + 1024]);
    float og = sigmoidf(g[j + 1536]);
    float c = fg * g_c[idx] + ig * gg;
    float h = og * tanhf(c);
    g_c[idx] = c;
    g_h[idx] = h;
}

// S5: logits = h_new @ out_w^T + out_b  (write to output) + per-block argmax
__global__ void k_logits(const float* __restrict__ out_w, const float* __restrict__ out_b,
                         float* __restrict__ dec_t /* dec + t*VV */) {
    __shared__ float sm[SM_FLOATS];
    float acc[8][2]; acc_zero(acc);
    const int bx = blockIdx.x;                     // 157 blocks
    const int col0 = bx * 64;
    const int nvalid = min(64, VV - col0);
    gemm32_core(g_h, HH, out_w, HH, HH, col0, nvalid, acc, sm, sm + 32 * 33);
    const int tx = threadIdx.x & 31, rq = threadIdx.x >> 5;
    #pragma unroll
    for (int i = 0; i < 8; ++i) {
        const int r = rq * 8 + i;
        float bv = -INFINITY; int bi = INT_MAX;
        #pragma unroll
        for (int j = 0; j < 2; ++j) {
            int cl = tx * 2 + j;
            if (cl < nvalid) {
                int c = col0 + cl;
                float vv = acc[i][j] + out_b[c];
                dec_t[(size_t)r * TT * VV + c] = vv;
                if (vv > bv) { bv = vv; bi = c; }
            }
        }
        #pragma unroll
        for (int off = 16; off; off >>= 1) {
            float ov = __shfl_xor_sync(0xffffffffu, bv, off);
            int   oi = __shfl_xor_sync(0xffffffffu, bi, off);
            if (ov > bv || (ov == bv && oi < bi)) { bv = ov; bi = oi; }
        }
        if (tx == 0) { g_bmv[r * NBLK_LOG + bx] = bv; g_bmi[r * NBLK_LOG + bx] = bi; }
    }
}

// S6: finalize argmax, gather next input embedding
__global__ void k_argmax(const float* __restrict__ emb) {
    const int b = blockIdx.x;
    const int tid = threadIdx.x;                   // 256
    __shared__ float sv[256];
    __shared__ int   si[256];
    float bv = -INFINITY; int bi = INT_MAX;
    for (int i = tid; i < NBLK_LOG; i += 256) {
        float v = g_bmv[b * NBLK_LOG + i];
        int   ix = g_bmi[b * NBLK_LOG + i];
        if (v > bv || (v == bv && ix < bi)) { bv = v; bi = ix; }
    }
    sv[tid] = bv; si[tid] = bi; __syncthreads();
    for (int st = 128; st > 0; st >>= 1) {
        if (tid < st) {
            float ov = sv[tid + st]; int oi = si[tid + st];
            if (ov > sv[tid] || (ov == sv[tid] && oi < si[tid])) { sv[tid] = ov; si[tid] = oi; }
        }
        __syncthreads();
    }
    const int best = si[0];
    const float* er = emb + (size_t)best * EE;
    for (int e = tid; e < EE; e += 256) g_inp[b * EE + e] = er[e];
}

__global__ void k_copyhc(float* __restrict__ hout, float* __restrict__ cout) {
    int idx = blockIdx.x * 256 + threadIdx.x;      // 2*BB*HH = 32768
    if (idx < BB * HH) hout[idx] = g_h[idx];
    else if (idx < 2 * BB * HH) cout[idx - BB * HH] = g_c[idx - BB * HH];
}

// ---------------------------------------------------------------------------
extern "C" void kernel_launch(void* const* d_in, const int* in_sizes, int n_in,
                              void* d_out, int out_size) {
    const float* feat   = (const float*)d_in[0];
    // d_in[1] = caption (unused), d_in[2] = max_caption (fixed 80)
    const float* emb    = (const float*)d_in[3];
    const float* W1_w   = (const float*)d_in[4];
    const float* W1_b   = (const float*)d_in[5];
    const float* W2_w   = (const float*)d_in[6];
    const float* W2_b   = (const float*)d_in[7];
    const float* Va_w   = (const float*)d_in[8];
    const float* Va_b   = (const float*)d_in[9];
    const float* Wih    = (const float*)d_in[10];
    const float* Whh    = (const float*)d_in[11];
    const float* bih    = (const float*)d_in[12];
    const float* bhh    = (const float*)d_in[13];
    const float* out_w  = (const float*)d_in[14];
    const float* out_b  = (const float*)d_in[15];
    const float* ihw    = (const float*)d_in[16];
    const float* ihb    = (const float*)d_in[17];
    const float* icw    = (const float*)d_in[18];
    const float* icb    = (const float*)d_in[19];
    const float* gate_w = (const float*)d_in[20];
    const float* gate_b = (const float*)d_in[21];

    float* out  = (float*)d_out;
    float* dec  = out;                                   // [B, T, V]
    float* hout = out + (size_t)BB * TT * VV;            // [B, H]
    float* cout = hout + (size_t)BB * HH;                // [B, H]
    float* attn = cout + (size_t)BB * HH;                // [B, T, P]

    k_mean<<<160, 256>>>(feat);
    k_inithc<<<16, 128>>>(ihw, ihb, icw, icb);
    k_inp0<<<64, 256>>>(emb);
    k_encproj<<<dim3(8, 196), 128>>>(feat, W2_w, W2_b);

    for (int t = 0; t < TT; ++t) {
        k_hproj<<<60, 128>>>(W1_w, W1_b, gate_w, gate_b, Whh, Wih, bih, bhh);
        k_attn<<<32, 256>>>(Va_w, Va_b, attn + (size_t)t * PP);
        k_context<<<320, 128>>>(feat);
        k_gates<<<32, 128>>>(Wih);
        k_lstm<<<64, 256>>>();
        k_logits<<<NBLK_LOG, 128>>>(out_w, out_b, dec + (size_t)t * VV);
        k_argmax<<<32, 256>>>(emb);
    }
    k_copyhc<<<128, 256>>>(hout, cout);
}

// round 3
// speedup vs baseline: 1.3833x; 1.3833x over previous
#include <cuda_runtime.h>
#include <math.h>
#include <limits.h>

#define BB 32
#define HH 512
#define EE 512
#define VV 10000
#define FF 1280
#define PP 196
#define TT 80
#define G4 2048                  // 4*H
#define XD 1792                  // E+F
#define NBLK_LOG ((VV + 63) / 64)  // 157

// ---------------- scratch ---------------------------------------------------
__device__ float g_mean[BB * FF];
__device__ float g_h[BB * HH];
__device__ float g_c[BB * HH];
__device__ float g_hid[BB * HH];
__device__ float g_glin[BB * FF];
__device__ float g_gates[BB * G4];      // holds g0 (= h@Whh + inp@WihE + biases) after K1
__device__ float g_sc[BB * PP];
__device__ float g_ctx[BB * FF];
__device__ float g_encproj[BB * PP * HH];
__device__ unsigned long long g_best[BB];

__device__ __forceinline__ float sigmoidf(float x) { return 1.0f / (1.0f + expf(-x)); }

// monotonic float->uint key (order-preserving)
__device__ __forceinline__ unsigned int fkey(float f) {
    unsigned int u = __float_as_uint(f);
    return (u & 0x80000000u) ? ~u : (u | 0x80000000u);
}

// ---------------------------------------------------------------------------
// Double-buffered 32x64 GEMM tile core. blockDim = 128, K % 32 == 0.
// A rows via rowoff[] (element offsets, smem). W is [rows x ldw], K-contiguous.
// MODE 0: W row = col0 + cl (cl<nvalid valid).  MODE 1: W row = (cl>>4)*512 + j0 + (cl&15).
// acc[i][j]: row rq*8+i, tile col tx*2+j.
// As: 32*33 floats (layout [k][row]), Ws: 32*66 floats (layout [k][col]).
// ---------------------------------------------------------------------------
template<int MODE>
__device__ __forceinline__ void gemm_db(
    const float* __restrict__ A, const unsigned int* __restrict__ rowoff,
    const float* __restrict__ W, int ldw, int K,
    int col0, int nvalid, int j0,
    float acc[8][2], float* As, float* Ws)
{
    const int tid = threadIdx.x;
    const int tx = tid & 31, rq = tid >> 5;

    const float* ap[2];
    #pragma unroll
    for (int v = 0; v < 2; ++v) {
        int idx = tid + v * 128;
        ap[v] = A + rowoff[idx >> 3] + (idx & 7) * 4;
    }
    const float* wp[4];
    bool wv[4];
    #pragma unroll
    for (int v = 0; v < 4; ++v) {
        int idx = tid + v * 128;
        int col = idx >> 3;
        int wr;
        if (MODE == 0) { wr = col0 + col; wv[v] = (col < nvalid); }
        else           { wr = ((col >> 4) << 9) + j0 + (col & 15); wv[v] = true; }
        wp[v] = W + (size_t)wr * ldw + (idx & 7) * 4;
    }

    float4 ra[2], rw[4];
    #pragma unroll
    for (int v = 0; v < 2; ++v) ra[v] = *(const float4*)(ap[v]);
    #pragma unroll
    for (int v = 0; v < 4; ++v)
        rw[v] = wv[v] ? *(const float4*)(wp[v]) : make_float4(0.f, 0.f, 0.f, 0.f);

    for (int k0 = 0; k0 < K; k0 += 32) {
        __syncthreads();
        #pragma unroll
        for (int v = 0; v < 2; ++v) {
            int idx = tid + v * 128;
            int row = idx >> 3, kq = idx & 7;
            As[(kq * 4 + 0) * 33 + row] = ra[v].x;
            As[(kq * 4 + 1) * 33 + row] = ra[v].y;
            As[(kq * 4 + 2) * 33 + row] = ra[v].z;
            As[(kq * 4 + 3) * 33 + row] = ra[v].w;
        }
        #pragma unroll
        for (int v = 0; v < 4; ++v) {
            int idx = tid + v * 128;
            int col = idx >> 3, kq = idx & 7;
            Ws[(kq * 4 + 0) * 66 + col] = rw[v].x;
            Ws[(kq * 4 + 1) * 66 + col] = rw[v].y;
            Ws[(kq * 4 + 2) * 66 + col] = rw[v].z;
            Ws[(kq * 4 + 3) * 66 + col] = rw[v].w;
        }
        __syncthreads();
        const int kn = k0 + 32;
        if (kn < K) {
            #pragma unroll
            for (int v = 0; v < 2; ++v) ra[v] = *(const float4*)(ap[v] + kn);
            #pragma unroll
            for (int v = 0; v < 4; ++v)
                rw[v] = wv[v] ? *(const float4*)(wp[v] + kn) : make_float4(0.f, 0.f, 0.f, 0.f);
        }
        #pragma unroll
        for (int k = 0; k < 32; ++k) {
            const float2 w2 = *(const float2*)(&Ws[k * 66 + tx * 2]);
            #pragma unroll
            for (int i = 0; i < 8; ++i) {
                float a = As[k * 33 + rq * 8 + i];
                acc[i][0] += a * w2.x;
                acc[i][1] += a * w2.y;
            }
        }
    }
    __syncthreads();
}

__device__ __forceinline__ void acc_zero(float acc[8][2]) {
    #pragma unroll
    for (int i = 0; i < 8; ++i) { acc[i][0] = 0.f; acc[i][1] = 0.f; }
}

// ---------------------------------------------------------------------------
// setup kernels
// ---------------------------------------------------------------------------
__global__ void k_mean(const float* __restrict__ feat) {
    int idx = blockIdx.x * 256 + threadIdx.x;       // BB*FF = 40960
    if (idx >= BB * FF) return;
    int b = idx / FF, f = idx % FF;
    const float* p0 = feat + (size_t)b * PP * FF + f;
    float s = 0.f;
    #pragma unroll 4
    for (int p = 0; p < PP; ++p) s += p0[(size_t)p * FF];
    g_mean[idx] = s * (1.0f / PP);
}

__global__ void k_init() {
    if (threadIdx.x < BB) g_best[threadIdx.x] = (unsigned long long)(0xffffffffu - 1u); // token = SOS = 1
}

__global__ void k_inithc(const float* __restrict__ ihw, const float* __restrict__ ihb,
                         const float* __restrict__ icw, const float* __restrict__ icb) {
    __shared__ float As[32 * 33], Ws[32 * 66];
    __shared__ unsigned int ro[32];
    float acc[8][2]; acc_zero(acc);
    int bx = blockIdx.x;
    bool ish = bx < 8;
    int col0 = (ish ? bx : bx - 8) * 64;
    const float* W = ish ? ihw : icw;
    const float* bias = ish ? ihb : icb;
    float* C = ish ? g_h : g_c;
    if (threadIdx.x < 32) ro[threadIdx.x] = threadIdx.x * FF;
    __syncthreads();
    gemm_db<0>(g_mean, ro, W, FF, FF, col0, 64, 0, acc, As, Ws);
    const int tx = threadIdx.x & 31, rq = threadIdx.x >> 5;
    #pragma unroll
    for (int i = 0; i < 8; ++i)
        #pragma unroll
        for (int j = 0; j < 2; ++j) {
            int c = col0 + tx * 2 + j;
            C[(rq * 8 + i) * HH + c] = acc[i][j] + bias[c];
        }
}

__global__ void k_encproj(const float* __restrict__ feat,
                          const float* __restrict__ W2_w, const float* __restrict__ W2_b) {
    __shared__ float As[32 * 33], Ws[32 * 66];
    __shared__ unsigned int ro[32];
    float acc[8][2]; acc_zero(acc);
    int col0 = blockIdx.x * 64;
    int m0 = blockIdx.y * 32;
    if (threadIdx.x < 32) ro[threadIdx.x] = threadIdx.x * FF;
    __syncthreads();
    gemm_db<0>(feat + (size_t)m0 * FF, ro, W2_w, FF, FF, col0, 64, 0, acc, As, Ws);
    const int tx = threadIdx.x & 31, rq = threadIdx.x >> 5;
    #pragma unroll
    for (int i = 0; i < 8; ++i)
        #pragma unroll
        for (int j = 0; j < 2; ++j) {
            int c = col0 + tx * 2 + j;
            g_encproj[(size_t)(m0 + rq * 8 + i) * HH + c] = acc[i][j] + W2_b[c];
        }
}

// ---------------------------------------------------------------------------
// per-step kernels (5 per step)
// ---------------------------------------------------------------------------
// K1: hid = h@W1^T+b1 (bx 0-7); glin = h@gate_w^T+gate_b (bx 8-27);
//     g_gates = h@Whh^T + emb[tok]@WihE^T + bih + bhh (bx 28-59)
__global__ void k_hproj(const float* __restrict__ emb,
                        const float* __restrict__ W1_w, const float* __restrict__ W1_b,
                        const float* __restrict__ gate_w, const float* __restrict__ gate_b,
                        const float* __restrict__ Whh, const float* __restrict__ Wih,
                        const float* __restrict__ bih, const float* __restrict__ bhh) {
    __shared__ float As[32 * 33], Ws[32 * 66];
    __shared__ unsigned int ro[32];
    float acc[8][2]; acc_zero(acc);
    const int bx = blockIdx.x;
    const int tid = threadIdx.x;
    const int tx = tid & 31, rq = tid >> 5;
    if (tid < 32) ro[tid] = tid * HH;
    __syncthreads();
    if (bx < 8) {
        int col0 = bx * 64;
        gemm_db<0>(g_h, ro, W1_w, HH, HH, col0, 64, 0, acc, As, Ws);
        #pragma unroll
        for (int i = 0; i < 8; ++i)
            #pragma unroll
            for (int j = 0; j < 2; ++j) {
                int c = col0 + tx * 2 + j;
                g_hid[(rq * 8 + i) * HH + c] = acc[i][j] + W1_b[c];
            }
    } else if (bx < 28) {
        int col0 = (bx - 8) * 64;
        gemm_db<0>(g_h, ro, gate_w, HH, HH, col0, 64, 0, acc, As, Ws);
        #pragma unroll
        for (int i = 0; i < 8; ++i)
            #pragma unroll
            for (int j = 0; j < 2; ++j) {
                int c = col0 + tx * 2 + j;
                g_glin[(rq * 8 + i) * FF + c] = acc[i][j] + gate_b[c];
            }
    } else {
        int col0 = (bx - 28) * 64;
        gemm_db<0>(g_h, ro, Whh, HH, HH, col0, 64, 0, acc, As, Ws);
        if (tid < 32) {
            unsigned int tok = 0xffffffffu - (unsigned int)(g_best[tid] & 0xffffffffull);
            ro[tid] = tok * EE;
        }
        __syncthreads();
        gemm_db<0>(emb, ro, Wih, XD, EE, col0, 64, 0, acc, As, Ws);
        #pragma unroll
        for (int i = 0; i < 8; ++i)
            #pragma unroll
            for (int j = 0; j < 2; ++j) {
                int c = col0 + tx * 2 + j;
                g_gates[(rq * 8 + i) * G4 + c] = acc[i][j] + bih[c] + bhh[c];
            }
    }
}

// K2: scores[b,p] = relu(hid[b]+encproj[b,p]) . Va + Va_b  ; grid (7, 32), 256 thr
__global__ void k_scores(const float* __restrict__ Va_w, const float* __restrict__ Va_b) {
    const int b = blockIdx.y;
    const int p0 = blockIdx.x * 28;
    const int tid = threadIdx.x;
    __shared__ float hid_s[HH], va_s[HH];
    for (int i = tid; i < HH; i += 256) { hid_s[i] = g_hid[b * HH + i]; va_s[i] = Va_w[i]; }
    __syncthreads();
    const int wid = tid >> 5, ln = tid & 31;
    const float vb = Va_b[0];
    for (int p = p0 + wid; p < p0 + 28; p += 8) {
        const float* ep = g_encproj + ((size_t)b * PP + p) * HH;
        float s = 0.f;
        #pragma unroll 4
        for (int h = ln; h < HH; h += 32) {
            float t0 = hid_s[h] + ep[h];
            if (t0 > 0.f) s += t0 * va_s[h];
        }
        #pragma unroll
        for (int off = 16; off; off >>= 1) s += __shfl_xor_sync(0xffffffffu, s, off);
        if (ln == 0) g_sc[b * PP + p] = s + vb;
    }
}

// K3: softmax(scores) -> weights (per-block redundant), context = w^T @ feat, *sigmoid(glin)
__global__ void k_ctx(const float* __restrict__ feat, float* __restrict__ attn_t) {
    const int bx = blockIdx.x;                     // 320 = 32 b * 10 ftile
    const int b = bx / 10, f0 = (bx % 10) * 128;
    const int tid = threadIdx.x;                   // 128
    __shared__ float ws[PP];
    __shared__ float red[128];
    // load scores
    float v0 = (tid < PP) ? g_sc[b * PP + tid] : -INFINITY;
    float v1 = (tid + 128 < PP) ? g_sc[b * PP + tid + 128] : -INFINITY;
    red[tid] = fmaxf(v0, v1); __syncthreads();
    for (int st = 64; st > 0; st >>= 1) { if (tid < st) red[tid] = fmaxf(red[tid], red[tid + st]); __syncthreads(); }
    const float mx = red[0];
    __syncthreads();
    float e0 = (tid < PP) ? expf(v0 - mx) : 0.f;
    float e1 = (tid + 128 < PP) ? expf(v1 - mx) : 0.f;
    red[tid] = e0 + e1; __syncthreads();
    for (int st = 64; st > 0; st >>= 1) { if (tid < st) red[tid] += red[tid + st]; __syncthreads(); }
    const float inv = 1.0f / red[0];
    if (tid < PP) ws[tid] = e0 * inv;
    if (tid + 128 < PP) ws[tid + 128] = e1 * inv;
    __syncthreads();
    if (f0 == 0) {  // one tile per batch writes attention weights out
        for (int p = tid; p < PP; p += 128) attn_t[(size_t)b * TT * PP + p] = ws[p];
    }
    const int f = f0 + tid;
    const float* fb = feat + (size_t)b * PP * FF + f;
    float acc = 0.f;
    #pragma unroll 4
    for (int p = 0; p < PP; ++p) acc += ws[p] * fb[(size_t)p * FF];
    g_ctx[b * FF + f] = acc * sigmoidf(g_glin[b * FF + f]);
}

// K4: gates += ctx @ WihF^T, then LSTM elementwise; also resets g_best. 32 blocks, j0=bx*16
__global__ void k_gates_lstm(const float* __restrict__ Wih) {
    __shared__ float As[32 * 33], Ws[32 * 66];
    __shared__ unsigned int ro[32];
    __shared__ float gs[32 * 64];
    float acc[8][2]; acc_zero(acc);
    const int bx = blockIdx.x;
    const int tid = threadIdx.x;
    const int j0 = bx * 16;
    if (tid < 32) ro[tid] = tid * FF;
    __syncthreads();
    gemm_db<1>(g_ctx, ro, Wih + EE, XD, FF, 0, 64, j0, acc, As, Ws);
    const int tx = tid & 31, rq = tid >> 5;
    #pragma unroll
    for (int i = 0; i < 8; ++i)
        #pragma unroll
        for (int j = 0; j < 2; ++j) {
            int cl = tx * 2 + j;
            int ac = ((cl >> 4) << 9) + j0 + (cl & 15);
            int r = rq * 8 + i;
            gs[r * 64 + cl] = acc[i][j] + g_gates[r * G4 + ac];
        }
    if (bx == 0 && tid < 32) g_best[tid] = 0ull;   // reset argmax accumulator for K5
    __syncthreads();
    #pragma unroll
    for (int s = 0; s < 4; ++s) {
        int q = tid + s * 128;                     // 512 items: (r, jj)
        int r = q >> 4, jj = q & 15;
        float ig = sigmoidf(gs[r * 64 + jj]);
        float fg = sigmoidf(gs[r * 64 + 16 + jj]);
        float gg = tanhf(gs[r * 64 + 32 + jj]);
        float og = sigmoidf(gs[r * 64 + 48 + jj]);
        int idx = r * HH + j0 + jj;
        float c = fg * g_c[idx] + ig * gg;
        g_c[idx] = c;
        g_h[idx] = og * tanhf(c);
    }
}

// K5: logits = h@out_w^T + out_b -> dec output; fused argmax via atomicMax(packed)
__global__ void k_logits(const float* __restrict__ out_w, const float* __restrict__ out_b,
                         float* __restrict__ dec_t) {
    __shared__ float As[32 * 33], Ws[32 * 66];
    __shared__ unsigned int ro[32];
    float acc[8][2]; acc_zero(acc);
    const int bx = blockIdx.x;                     // 157
    const int col0 = bx * 64;
    const int nvalid = min(64, VV - col0);
    const int tid = threadIdx.x;
    if (tid < 32) ro[tid] = tid * HH;
    __syncthreads();
    gemm_db<0>(g_h, ro, out_w, HH, HH, col0, nvalid, 0, acc, As, Ws);
    const int tx = tid & 31, rq = tid >> 5;
    #pragma unroll
    for (int i = 0; i < 8; ++i) {
        const int r = rq * 8 + i;
        unsigned long long pk = 0ull;
        #pragma unroll
        for (int j = 0; j < 2; ++j) {
            int cl = tx * 2 + j;
            if (cl < nvalid) {
                int c = col0 + cl;
                float vv = acc[i][j] + out_b[c];
                dec_t[(size_t)r * TT * VV + c] = vv;
                unsigned long long p = ((unsigned long long)fkey(vv) << 32) | (0xffffffffu - (unsigned int)c);
                if (p > pk) pk = p;
            }
        }
        #pragma unroll
        for (int off = 16; off; off >>= 1) {
            unsigned long long o = __shfl_xor_sync(0xffffffffu, pk, off);
            if (o > pk) pk = o;
        }
        if (tx == 0) atomicMax(&g_best[r], pk);
    }
}

__global__ void k_copyhc(float* __restrict__ hout, float* __restrict__ cout) {
    int idx = blockIdx.x * 256 + threadIdx.x;
    if (idx < BB * HH) hout[idx] = g_h[idx];
    else if (idx < 2 * BB * HH) cout[idx - BB * HH] = g_c[idx - BB * HH];
}

// ---------------------------------------------------------------------------
extern "C" void kernel_launch(void* const* d_in, const int* in_sizes, int n_in,
                              void* d_out, int out_size) {
    const float* feat   = (const float*)d_in[0];
    const float* emb    = (const float*)d_in[3];
    const float* W1_w   = (const float*)d_in[4];
    const float* W1_b   = (const float*)d_in[5];
    const float* W2_w   = (const float*)d_in[6];
    const float* W2_b   = (const float*)d_in[7];
    const float* Va_w   = (const float*)d_in[8];
    const float* Va_b   = (const float*)d_in[9];
    const float* Wih    = (const float*)d_in[10];
    const float* Whh    = (const float*)d_in[11];
    const float* bih    = (const float*)d_in[12];
    const float* bhh    = (const float*)d_in[13];
    const float* out_w  = (const float*)d_in[14];
    const float* out_b  = (const float*)d_in[15];
    const float* ihw    = (const float*)d_in[16];
    const float* ihb    = (const float*)d_in[17];
    const float* icw    = (const float*)d_in[18];
    const float* icb    = (const float*)d_in[19];
    const float* gate_w = (const float*)d_in[20];
    const float* gate_b = (const float*)d_in[21];

    float* out  = (float*)d_out;
    float* dec  = out;                                   // [B, T, V]
    float* hout = out + (size_t)BB * TT * VV;            // [B, H]
    float* cout = hout + (size_t)BB * HH;                // [B, H]
    float* attn = cout + (size_t)BB * HH;                // [B, T, P]

    k_mean<<<160, 256>>>(feat);
    k_init<<<1, 32>>>();
    k_inithc<<<16, 128>>>(ihw, ihb, icw, icb);
    k_encproj<<<dim3(8, 196), 128>>>(feat, W2_w, W2_b);

    for (int t = 0; t < TT; ++t) {
        k_hproj<<<60, 128>>>(emb, W1_w, W1_b, gate_w, gate_b, Whh, Wih, bih, bhh);
        k_scores<<<dim3(7, 32), 256>>>(Va_w, Va_b);
        k_ctx<<<320, 128>>>(feat, attn + (size_t)t * PP);
        k_gates_lstm<<<32, 128>>>(Wih);
        k_logits<<<NBLK_LOG, 128>>>(out_w, out_b, dec + (size_t)t * VV);
    }
    k_copyhc<<<128, 256>>>(hout, cout);
}

// round 4
// speedup vs baseline: 1.7730x; 1.2818x over previous
#include <cuda_runtime.h>
#include <math.h>
#include <limits.h>

#define BB 32
#define HH 512
#define EE 512
#define VV 10000
#define FF 1280
#define PP 196
#define TT 80
#define G4 2048
#define XD 1792

// ---------------- scratch ---------------------------------------------------
__device__ float g_mean[BB * FF];
__device__ float g_h[BB * HH];
__device__ float g_c[BB * HH];
__device__ float g_hid[BB * HH];
__device__ float g_glin[BB * FF];
__device__ float g_g0a[BB * G4];
__device__ float g_g0b[BB * G4];
__device__ float g_sc[BB * PP];
__device__ float g_ctx[BB * FF];
__device__ float g_encproj[BB * PP * HH];
__device__ unsigned long long g_best[BB];

__device__ __forceinline__ float sigmoidf(float x) { return 1.0f / (1.0f + expf(-x)); }

__device__ __forceinline__ unsigned int fkey(float f) {
    unsigned int u = __float_as_uint(f);
    return (u & 0x80000000u) ? ~u : (u | 0x80000000u);
}

// ---------------------------------------------------------------------------
// GEMM tile core, 32 rows x (NC*32) cols, blockDim = 128, K % 32 == 0.
// As layout [k][row], stride 36 floats -> 8-row reads = 2 broadcast LDS.128.
// Ws layout [k][col], stride 66 (NC=2) / 33 (NC=1).
// MODE 0: W row = col0 + col (col < nvalid). MODE 1: row = (col>>3)*512 + j0 + (col&7).
// Double-buffered in registers.
// ---------------------------------------------------------------------------
template<int NC, int MODE>
__device__ __forceinline__ void gemm2(
    const float* __restrict__ A, const unsigned int* __restrict__ rowoff,
    const float* __restrict__ W, int ldw, int K,
    int col0, int nvalid, int j0,
    float acc[8][NC], float* As, float* Ws)
{
    constexpr int NWV = (NC == 2) ? 4 : 2;
    constexpr int WST = (NC == 2) ? 66 : 33;
    const int tid = threadIdx.x;
    const int tx = tid & 31, rq = tid >> 5;

    const float* ap[2];
    #pragma unroll
    for (int v = 0; v < 2; ++v) {
        int idx = tid + v * 128;
        ap[v] = A + rowoff[idx >> 3] + (idx & 7) * 4;
    }
    const float* wp[NWV]; bool wv[NWV];
    #pragma unroll
    for (int v = 0; v < NWV; ++v) {
        int idx = tid + v * 128;
        int col = idx >> 3;
        int wr;
        if (MODE == 0) { wr = col0 + col; wv[v] = (col < nvalid); }
        else           { wr = ((col >> 3) << 9) + j0 + (col & 7); wv[v] = true; }
        wp[v] = W + (size_t)wr * ldw + (idx & 7) * 4;
    }

    float4 ra[2], rw[NWV];
    #pragma unroll
    for (int v = 0; v < 2; ++v) ra[v] = *(const float4*)(ap[v]);
    #pragma unroll
    for (int v = 0; v < NWV; ++v)
        rw[v] = wv[v] ? *(const float4*)(wp[v]) : make_float4(0.f, 0.f, 0.f, 0.f);

    for (int k0 = 0; k0 < K; k0 += 32) {
        __syncthreads();
        #pragma unroll
        for (int v = 0; v < 2; ++v) {
            int idx = tid + v * 128;
            int row = idx >> 3, kq = idx & 7;
            As[(kq * 4 + 0) * 36 + row] = ra[v].x;
            As[(kq * 4 + 1) * 36 + row] = ra[v].y;
            As[(kq * 4 + 2) * 36 + row] = ra[v].z;
            As[(kq * 4 + 3) * 36 + row] = ra[v].w;
        }
        #pragma unroll
        for (int v = 0; v < NWV; ++v) {
            int idx = tid + v * 128;
            int col = idx >> 3, kq = idx & 7;
            Ws[(kq * 4 + 0) * WST + col] = rw[v].x;
            Ws[(kq * 4 + 1) * WST + col] = rw[v].y;
            Ws[(kq * 4 + 2) * WST + col] = rw[v].z;
            Ws[(kq * 4 + 3) * WST + col] = rw[v].w;
        }
        __syncthreads();
        const int kn = k0 + 32;
        if (kn < K) {
            #pragma unroll
            for (int v = 0; v < 2; ++v) ra[v] = *(const float4*)(ap[v] + kn);
            #pragma unroll
            for (int v = 0; v < NWV; ++v)
                rw[v] = wv[v] ? *(const float4*)(wp[v] + kn) : make_float4(0.f, 0.f, 0.f, 0.f);
        }
        #pragma unroll
        for (int k = 0; k < 32; ++k) {
            const float4 a0 = *(const float4*)&As[k * 36 + rq * 8];
            const float4 a1 = *(const float4*)&As[k * 36 + rq * 8 + 4];
            float av[8] = {a0.x, a0.y, a0.z, a0.w, a1.x, a1.y, a1.z, a1.w};
            if (NC == 2) {
                const float2 w2 = *(const float2*)&Ws[k * 66 + tx * 2];
                #pragma unroll
                for (int i = 0; i < 8; ++i) {
                    acc[i][0] += av[i] * w2.x;
                    acc[i][1] += av[i] * w2.y;
                }
            } else {
                const float w = Ws[k * 33 + tx];
                #pragma unroll
                for (int i = 0; i < 8; ++i) acc[i][0] += av[i] * w;
            }
        }
    }
    __syncthreads();
}

template<int NC>
__device__ __forceinline__ void acc_zero(float acc[8][NC]) {
    #pragma unroll
    for (int i = 0; i < 8; ++i)
        #pragma unroll
        for (int j = 0; j < NC; ++j) acc[i][j] = 0.f;
}

#define SMEM_NC2 __shared__ float As[32 * 36], Ws[32 * 66]; __shared__ unsigned int ro[32];
#define SMEM_NC1 __shared__ float As[32 * 36], Ws[32 * 33]; __shared__ unsigned int ro[32];

// ---------------------------------------------------------------------------
// setup
// ---------------------------------------------------------------------------
__global__ void k_mean(const float* __restrict__ feat) {
    int idx = blockIdx.x * 256 + threadIdx.x;
    if (blockIdx.x == 0 && threadIdx.x < BB)
        g_best[threadIdx.x] = (unsigned long long)(0xffffffffu - 1u);   // token = SOS = 1
    if (idx >= BB * FF) return;
    int b = idx / FF, f = idx % FF;
    const float* p0 = feat + (size_t)b * PP * FF + f;
    float s = 0.f;
    #pragma unroll 4
    for (int p = 0; p < PP; ++p) s += p0[(size_t)p * FF];
    g_mean[idx] = s * (1.0f / PP);
}

__global__ void k_inithc(const float* __restrict__ ihw, const float* __restrict__ ihb,
                         const float* __restrict__ icw, const float* __restrict__ icb) {
    SMEM_NC2
    float acc[8][2]; acc_zero<2>(acc);
    int bx = blockIdx.x;
    bool ish = bx < 8;
    int col0 = (ish ? bx : bx - 8) * 64;
    const float* W = ish ? ihw : icw;
    const float* bias = ish ? ihb : icb;
    float* C = ish ? g_h : g_c;
    if (threadIdx.x < 32) ro[threadIdx.x] = threadIdx.x * FF;
    __syncthreads();
    gemm2<2, 0>(g_mean, ro, W, FF, FF, col0, 64, 0, acc, As, Ws);
    const int tx = threadIdx.x & 31, rq = threadIdx.x >> 5;
    #pragma unroll
    for (int i = 0; i < 8; ++i)
        #pragma unroll
        for (int j = 0; j < 2; ++j) {
            int c = col0 + tx * 2 + j;
            C[(rq * 8 + i) * HH + c] = acc[i][j] + bias[c];
        }
}

__global__ void k_encproj(const float* __restrict__ feat,
                          const float* __restrict__ W2_w, const float* __restrict__ W2_b) {
    SMEM_NC2
    float acc[8][2]; acc_zero<2>(acc);
    int col0 = blockIdx.x * 64;
    int m0 = blockIdx.y * 32;
    if (threadIdx.x < 32) ro[threadIdx.x] = threadIdx.x * FF;
    __syncthreads();
    gemm2<2, 0>(feat + (size_t)m0 * FF, ro, W2_w, FF, FF, col0, 64, 0, acc, As, Ws);
    const int tx = threadIdx.x & 31, rq = threadIdx.x >> 5;
    #pragma unroll
    for (int i = 0; i < 8; ++i)
        #pragma unroll
        for (int j = 0; j < 2; ++j) {
            int c = col0 + tx * 2 + j;
            g_encproj[(size_t)(m0 + rq * 8 + i) * HH + c] = acc[i][j] + W2_b[c];
        }
}

// ---------------------------------------------------------------------------
// per-step kernels
// ---------------------------------------------------------------------------
// K1: 92 blocks. bx<8: hid=h@W1^T+b1. bx<28: glin=h@gate_w^T+gate_b.
//     bx<60: g0a=h@Whh^T+bih+bhh. bx<92: g0b=emb[tok]@WihE^T.
__global__ void k_hproj(const float* __restrict__ emb,
                        const float* __restrict__ W1_w, const float* __restrict__ W1_b,
                        const float* __restrict__ gate_w, const float* __restrict__ gate_b,
                        const float* __restrict__ Whh, const float* __restrict__ Wih,
                        const float* __restrict__ bih, const float* __restrict__ bhh) {
    SMEM_NC2
    float acc[8][2]; acc_zero<2>(acc);
    const int bx = blockIdx.x;
    const int tid = threadIdx.x;
    const int tx = tid & 31, rq = tid >> 5;
    if (bx < 60) { if (tid < 32) ro[tid] = tid * HH; }
    else if (tid < 32) {
        unsigned int tok = 0xffffffffu - (unsigned int)(g_best[tid] & 0xffffffffull);
        ro[tid] = tok * EE;
    }
    __syncthreads();
    if (bx < 8) {
        int col0 = bx * 64;
        gemm2<2, 0>(g_h, ro, W1_w, HH, HH, col0, 64, 0, acc, As, Ws);
        #pragma unroll
        for (int i = 0; i < 8; ++i)
            #pragma unroll
            for (int j = 0; j < 2; ++j) {
                int c = col0 + tx * 2 + j;
                g_hid[(rq * 8 + i) * HH + c] = acc[i][j] + W1_b[c];
            }
    } else if (bx < 28) {
        int col0 = (bx - 8) * 64;
        gemm2<2, 0>(g_h, ro, gate_w, HH, HH, col0, 64, 0, acc, As, Ws);
        #pragma unroll
        for (int i = 0; i < 8; ++i)
            #pragma unroll
            for (int j = 0; j < 2; ++j) {
                int c = col0 + tx * 2 + j;
                g_glin[(rq * 8 + i) * FF + c] = acc[i][j] + gate_b[c];
            }
    } else if (bx < 60) {
        int col0 = (bx - 28) * 64;
        gemm2<2, 0>(g_h, ro, Whh, HH, HH, col0, 64, 0, acc, As, Ws);
        #pragma unroll
        for (int i = 0; i < 8; ++i)
            #pragma unroll
            for (int j = 0; j < 2; ++j) {
                int c = col0 + tx * 2 + j;
                g_g0a[(rq * 8 + i) * G4 + c] = acc[i][j] + bih[c] + bhh[c];
            }
    } else {
        int col0 = (bx - 60) * 64;
        gemm2<2, 0>(emb, ro, Wih, XD, EE, col0, 64, 0, acc, As, Ws);
        #pragma unroll
        for (int i = 0; i < 8; ++i)
            #pragma unroll
            for (int j = 0; j < 2; ++j) {
                int c = col0 + tx * 2 + j;
                g_g0b[(rq * 8 + i) * G4 + c] = acc[i][j];
            }
    }
}

// K2: scores[b,p] = relu(hid[b]+encproj[b,p]).Va + Va_b  ; grid (7, 32), 256 thr
__global__ void k_scores(const float* __restrict__ Va_w, const float* __restrict__ Va_b) {
    const int b = blockIdx.y;
    const int p0 = blockIdx.x * 28;
    const int tid = threadIdx.x;
    __shared__ float hid_s[HH], va_s[HH];
    for (int i = tid; i < HH; i += 256) { hid_s[i] = g_hid[b * HH + i]; va_s[i] = Va_w[i]; }
    __syncthreads();
    const int wid = tid >> 5, ln = tid & 31;
    const float vb = Va_b[0];
    for (int p = p0 + wid; p < p0 + 28; p += 8) {
        const float* ep = g_encproj + ((size_t)b * PP + p) * HH;
        float s = 0.f;
        #pragma unroll 4
        for (int h = ln; h < HH; h += 32) {
            float t0 = hid_s[h] + ep[h];
            if (t0 > 0.f) s += t0 * va_s[h];
        }
        #pragma unroll
        for (int off = 16; off; off >>= 1) s += __shfl_xor_sync(0xffffffffu, s, off);
        if (ln == 0) g_sc[b * PP + p] = s + vb;
    }
}

// K3: softmax -> weights; context = w^T @ feat; * sigmoid(glin)
__global__ void k_ctx(const float* __restrict__ feat, float* __restrict__ attn_t) {
    const int bx = blockIdx.x;                     // 320
    const int b = bx / 10, f0 = (bx % 10) * 128;
    const int tid = threadIdx.x;                   // 128
    __shared__ float ws[PP];
    __shared__ float red[128];
    float v0 = (tid < PP) ? g_sc[b * PP + tid] : -INFINITY;
    float v1 = (tid + 128 < PP) ? g_sc[b * PP + tid + 128] : -INFINITY;
    red[tid] = fmaxf(v0, v1); __syncthreads();
    for (int st = 64; st > 0; st >>= 1) { if (tid < st) red[tid] = fmaxf(red[tid], red[tid + st]); __syncthreads(); }
    const float mx = red[0];
    __syncthreads();
    float e0 = (tid < PP) ? expf(v0 - mx) : 0.f;
    float e1 = (tid + 128 < PP) ? expf(v1 - mx) : 0.f;
    red[tid] = e0 + e1; __syncthreads();
    for (int st = 64; st > 0; st >>= 1) { if (tid < st) red[tid] += red[tid + st]; __syncthreads(); }
    const float inv = 1.0f / red[0];
    if (tid < PP) ws[tid] = e0 * inv;
    if (tid + 128 < PP) ws[tid + 128] = e1 * inv;
    __syncthreads();
    if (f0 == 0) {
        for (int p = tid; p < PP; p += 128) attn_t[(size_t)b * TT * PP + p] = ws[p];
    }
    const int f = f0 + tid;
    const float* fb = feat + (size_t)b * PP * FF + f;
    float acc = 0.f;
    #pragma unroll 8
    for (int p = 0; p < PP; ++p) acc += ws[p] * fb[(size_t)p * FF];
    g_ctx[b * FF + f] = acc * sigmoidf(g_glin[b * FF + f]);
}

// K4: gates = ctx@WihF^T + g0a + g0b, LSTM elementwise. 64 blocks, j0 = bx*8.
__global__ void k_gates_lstm(const float* __restrict__ Wih) {
    SMEM_NC1
    __shared__ float gs[32 * 32];
    float acc[8][1]; acc_zero<1>(acc);
    const int bx = blockIdx.x;
    const int tid = threadIdx.x;
    const int j0 = bx * 8;
    if (tid < 32) ro[tid] = tid * FF;
    __syncthreads();
    gemm2<1, 1>(g_ctx, ro, Wih + EE, XD, FF, 0, 32, j0, acc, As, Ws);
    const int tx = tid & 31, rq = tid >> 5;
    {
        const int g = tx >> 3, jj = tx & 7;
        const int ac = (g << 9) + j0 + jj;
        #pragma unroll
        for (int i = 0; i < 8; ++i) {
            int r = rq * 8 + i;
            gs[r * 32 + tx] = acc[i][0] + g_g0a[r * G4 + ac] + g_g0b[r * G4 + ac];
        }
    }
    if (bx == 0 && tid < 32) g_best[tid] = 0ull;   // reset argmax accumulator for K5
    __syncthreads();
    #pragma unroll
    for (int s = 0; s < 2; ++s) {
        int q = tid + s * 128;                     // 256 items: 32 rows x 8 jj
        int r = q >> 3, jj = q & 7;
        float ig = sigmoidf(gs[r * 32 + jj]);
        float fg = sigmoidf(gs[r * 32 + 8 + jj]);
        float gg = tanhf(gs[r * 32 + 16 + jj]);
        float og = sigmoidf(gs[r * 32 + 24 + jj]);
        int idx = r * HH + j0 + jj;
        float c = fg * g_c[idx] + ig * gg;
        g_c[idx] = c;
        g_h[idx] = og * tanhf(c);
    }
}

// K5: logits + fused argmax. 313 blocks, 32 cols each (last block 16).
__global__ void k_logits(const float* __restrict__ out_w, const float* __restrict__ out_b,
                         float* __restrict__ dec_t) {
    SMEM_NC1
    float acc[8][1]; acc_zero<1>(acc);
    const int bx = blockIdx.x;
    const int col0 = bx * 32;
    const int nvalid = min(32, VV - col0);
    const int tid = threadIdx.x;
    if (tid < 32) ro[tid] = tid * HH;
    __syncthreads();
    gemm2<1, 0>(g_h, ro, out_w, HH, HH, col0, nvalid, 0, acc, As, Ws);
    const int tx = tid & 31, rq = tid >> 5;
    const bool val = (tx < nvalid);
    const int c = col0 + tx;
    const float ob = val ? out_b[c] : 0.f;
    #pragma unroll
    for (int i = 0; i < 8; ++i) {
        const int r = rq * 8 + i;
        unsigned long long pk = 0ull;
        if (val) {
            float vv = acc[i][0] + ob;
            dec_t[(size_t)r * TT * VV + c] = vv;
            pk = ((unsigned long long)fkey(vv) << 32) | (0xffffffffu - (unsigned int)c);
        }
        #pragma unroll
        for (int off = 16; off; off >>= 1) {
            unsigned long long o = __shfl_xor_sync(0xffffffffu, pk, off);
            if (o > pk) pk = o;
        }
        if (tx == 0) atomicMax(&g_best[r], pk);
    }
}

__global__ void k_copyhc(float* __restrict__ hout, float* __restrict__ cout) {
    int idx = blockIdx.x * 256 + threadIdx.x;
    if (idx < BB * HH) hout[idx] = g_h[idx];
    else if (idx < 2 * BB * HH) cout[idx - BB * HH] = g_c[idx - BB * HH];
}

// ---------------------------------------------------------------------------
extern "C" void kernel_launch(void* const* d_in, const int* in_sizes, int n_in,
                              void* d_out, int out_size) {
    const float* feat   = (const float*)d_in[0];
    const float* emb    = (const float*)d_in[3];
    const float* W1_w   = (const float*)d_in[4];
    const float* W1_b   = (const float*)d_in[5];
    const float* W2_w   = (const float*)d_in[6];
    const float* W2_b   = (const float*)d_in[7];
    const float* Va_w   = (const float*)d_in[8];
    const float* Va_b   = (const float*)d_in[9];
    const float* Wih    = (const float*)d_in[10];
    const float* Whh    = (const float*)d_in[11];
    const float* bih    = (const float*)d_in[12];
    const float* bhh    = (const float*)d_in[13];
    const float* out_w  = (const float*)d_in[14];
    const float* out_b  = (const float*)d_in[15];
    const float* ihw    = (const float*)d_in[16];
    const float* ihb    = (const float*)d_in[17];
    const float* icw    = (const float*)d_in[18];
    const float* icb    = (const float*)d_in[19];
    const float* gate_w = (const float*)d_in[20];
    const float* gate_b = (const float*)d_in[21];

    float* out  = (float*)d_out;
    float* dec  = out;                                   // [B, T, V]
    float* hout = out + (size_t)BB * TT * VV;            // [B, H]
    float* cout = hout + (size_t)BB * HH;                // [B, H]
    float* attn = cout + (size_t)BB * HH;                // [B, T, P]

    k_mean<<<160, 256>>>(feat);
    k_inithc<<<16, 128>>>(ihw, ihb, icw, icb);
    k_encproj<<<dim3(8, 196), 128>>>(feat, W2_w, W2_b);

    for (int t = 0; t < TT; ++t) {
        k_hproj<<<92, 128>>>(emb, W1_w, W1_b, gate_w, gate_b, Whh, Wih, bih, bhh);
        k_scores<<<dim3(7, 32), 256>>>(Va_w, Va_b);
        k_ctx<<<320, 128>>>(feat, attn + (size_t)t * PP);
        k_gates_lstm<<<64, 128>>>(Wih);
        k_logits<<<313, 128>>>(out_w, out_b, dec + (size_t)t * VV);
    }
    k_copyhc<<<128, 256>>>(hout, cout);
}